// round 14
// baseline (speedup 1.0000x reference)
#include <cuda_runtime.h>

#define NB 256
#define NT 1024
#define ND0 32
#define NH 64
#define NM (NB * NT)

__device__ float g_gx0[(size_t)NM * 256];   // L0 gate pre-activations [tok][gate]

using ull = unsigned long long;

__device__ __forceinline__ void ffma2(ull& d, ull a, ull b) {
    asm("fma.rn.f32x2 %0, %1, %2, %0;" : "+l"(d) : "l"(a), "l"(b));
}
__device__ __forceinline__ ull packf2(float x, float y) {
    ull r; asm("mov.b64 %0, {%1, %2};" : "=l"(r) : "f"(x), "f"(y)); return r;
}
__device__ __forceinline__ float2 unpackf2(ull v) {
    float2 f; asm("mov.b64 {%0, %1}, %2;" : "=f"(f.x), "=f"(f.y) : "l"(v)); return f;
}
__device__ __forceinline__ float ftanh(float x) {
    float y; asm("tanh.approx.f32 %0, %1;" : "=f"(y) : "f"(x)); return y;
}
__device__ __forceinline__ float fsig(float x) {
    return fmaf(0.5f, ftanh(0.5f * x), 0.5f);
}
__device__ __forceinline__ void cp_async16(void* s, const void* g) {
    unsigned sa = (unsigned)__cvta_generic_to_shared(s);
    asm volatile("cp.async.cg.shared.global [%0], [%1], 16;" :: "r"(sa), "l"(g));
}

// ===================== layer-0 gate GEMM (proven, unchanged) =====================
__global__ __launch_bounds__(256) void gate_gemm32(
    const float* __restrict__ X,     // [M][32]
    const float* __restrict__ w_ih,  // [256][32]
    const float* __restrict__ b_ih,
    const float* __restrict__ b_hh,
    float* __restrict__ gx)          // [M][256]
{
    __shared__ __align__(16) ull   xdup[32][80];
    __shared__ __align__(16) float wT[32][264];

    const int tid = threadIdx.x;
    const size_t tok0 = (size_t)blockIdx.x * 64;

#pragma unroll
    for (int j = 0; j < 2; j++) {
        const int idx4 = tid + j * 256;
        const int tau = idx4 >> 3, kc = idx4 & 7;
        const int ts = tau + 2 * (tau >> 3);
        const float4 v = reinterpret_cast<const float4*>(X + (tok0 + tau) * 32)[kc];
        xdup[4 * kc + 0][ts] = packf2(v.x, v.x);
        xdup[4 * kc + 1][ts] = packf2(v.y, v.y);
        xdup[4 * kc + 2][ts] = packf2(v.z, v.z);
        xdup[4 * kc + 3][ts] = packf2(v.w, v.w);
    }
    {
        const float4* wr = reinterpret_cast<const float4*>(w_ih + tid * 32);
#pragma unroll
        for (int c = 0; c < 8; c++) {
            const float4 v = wr[c];
            wT[4 * c + 0][tid] = v.x;
            wT[4 * c + 1][tid] = v.y;
            wT[4 * c + 2][tid] = v.z;
            wT[4 * c + 3][tid] = v.w;
        }
    }

    const int tokg = tid & 7;
    const int gg   = tid >> 3;
    const int t0s = tokg * 10;
    const int t0  = tokg * 8;
    const int g0  = gg * 8;

    ull acc[8][4];
#pragma unroll
    for (int p = 0; p < 4; p++) {
        const ull bp = packf2(b_ih[g0 + 2 * p]     + b_hh[g0 + 2 * p],
                              b_ih[g0 + 2 * p + 1] + b_hh[g0 + 2 * p + 1]);
#pragma unroll
        for (int tk = 0; tk < 8; tk++) acc[tk][p] = bp;
    }

    __syncthreads();

#pragma unroll 4
    for (int k = 0; k < 32; k++) {
        const ulonglong2 wa = *reinterpret_cast<const ulonglong2*>(&wT[k][g0]);
        const ulonglong2 wb = *reinterpret_cast<const ulonglong2*>(&wT[k][g0 + 4]);
        const ull w01[4] = {wa.x, wa.y, wb.x, wb.y};
        const ulonglong2* xr = reinterpret_cast<const ulonglong2*>(&xdup[k][t0s]);
#pragma unroll
        for (int h = 0; h < 4; h++) {
            const ulonglong2 xv = xr[h];
#pragma unroll
            for (int p = 0; p < 4; p++) {
                ffma2(acc[2 * h][p],     xv.x, w01[p]);
                ffma2(acc[2 * h + 1][p], xv.y, w01[p]);
            }
        }
    }

#pragma unroll
    for (int tk = 0; tk < 8; tk++) {
        ulonglong2* dst =
            reinterpret_cast<ulonglong2*>(gx + (tok0 + t0 + tk) * 256 + g0);
        dst[0] = make_ulonglong2(acc[tk][0], acc[tk][1]);
        dst[1] = make_ulonglong2(acc[tk][2], acc[tk][3]);
    }
}

// ========== fused L0+L1: redundant per-warp cells, ONE barrier per step ==========
// 384 thr. L0 warps (q,lh): dot partial lanes l=tid&63, k-half q; cell lane
// cl=32q+laneid (both lh warps redundant). L1 warps (kq,lh): kq01 = h1 slice
// (track L0 c-state redundantly, using gx+p0buf), kq23 = h2 slice (track
// L1 d-state, using p1buf+bias). Each warp writes its own u-slice to a
// warp-PRIVATE smem buffer -> only __syncwarp between cell and dot.
// Partial buffers parity-double-buffered; one __syncthreads per step.
__global__ __launch_bounds__(384) void lstm_fused(
    const float* __restrict__ gx0,    // [B][T][256] (with L0 biases)
    const float* __restrict__ w_hh0,  // [256][64]
    const float* __restrict__ w_ih1,  // [256][64]
    const float* __restrict__ w_hh1,  // [256][64]
    const float* __restrict__ b_ih1,  // [256]
    const float* __restrict__ b_hh1,  // [256]
    const float* __restrict__ w_fc,   // [64]
    const float* __restrict__ b_fc,   // [1]
    float* __restrict__ out)          // [B]
{
    constexpr int PF = 7;

    __shared__ __align__(16) float gxs[8][2][256];         // gx0 ring (16 KB)
    __shared__ __align__(16) float p0buf[2][2][2][64][4];  // [par][q][s][l][g] 8 KB
    __shared__ __align__(16) float p1buf[2][4][2][64][4];  // [par][kq][s][l][g] 16 KB
    __shared__ __align__(16) float priv[12][2][40];        // [warp][s][32+pad]
    __shared__ float red[2][NH];

    const int tid  = threadIdx.x;
    const int wid  = tid >> 5;
    const int lane = tid & 31;
    const int b0   = blockIdx.x * 2;
    const bool isL0 = (tid < 128);

    const int q  = (tid >> 6) & 1;     // L0 k-half    (warp-constant)
    const int rt = tid - 128;
    const int kq = rt >> 6;            // L1 k-quarter (warp-constant)
    const int l  = tid & 63;           // dot partial lane (L1: rt&63 == tid&63)

    // cell lane this thread recomputes (its warp's u-slice)
    const int cl = isL0 ? (32 * q + lane)
                        : (kq < 2 ? 32 * kq + lane : 32 * (kq - 2) + lane);
    const bool isH1cell = isL0 || (kq < 2);   // h1-type cell (uses gx)

    // zero shared state
    for (int i = tid; i < 12 * 2 * 40; i += 384) (&priv[0][0][0])[i] = 0.0f;
    for (int i = tid; i < 2 * 2 * 2 * 64 * 4; i += 384) (&p0buf[0][0][0][0][0])[i] = 0.0f;
    for (int i = tid; i < 2 * 4 * 2 * 64 * 4; i += 384) (&p1buf[0][0][0][0][0])[i] = 0.0f;

    // ---- weights: 4 gate rows of lane l, my k-slice -> 128 regs ----
    ull w[4][16];
    float bi = 0.f, bf_ = 0.f, bg = 0.f, bo = 0.f;
    if (isL0) {
#pragma unroll
        for (int g4 = 0; g4 < 4; g4++) {
            const int row = 64 * g4 + l;
#pragma unroll
            for (int i = 0; i < 16; i++) {
                const int k = 32 * q + 2 * i;
                w[g4][i] = packf2(w_hh0[row * NH + k], w_hh0[row * NH + k + 1]);
            }
        }
    } else {
#pragma unroll
        for (int g4 = 0; g4 < 4; g4++) {
            const int row = 64 * g4 + l;
#pragma unroll
            for (int i = 0; i < 16; i++) {
                const int kk = 32 * kq + 2 * i;
                const float a = (kk < 64) ? w_ih1[row * 64 + kk]
                                          : w_hh1[row * 64 + kk - 64];
                const float b = (kk < 64) ? w_ih1[row * 64 + kk + 1]
                                          : w_hh1[row * 64 + kk - 63];
                w[g4][i] = packf2(a, b);
            }
        }
        if (kq >= 2) {   // h2 cells need L1 biases for lane cl
            bi  = b_ih1[cl]       + b_hh1[cl];
            bf_ = b_ih1[64 + cl]  + b_hh1[64 + cl];
            bg  = b_ih1[128 + cl] + b_hh1[128 + cl];
            bo  = b_ih1[192 + cl] + b_hh1[192 + cl];
        }
    }

    // gx ring loaders: L0 q==1 threads (warps 2,3)
    const bool isload = isL0 && (q == 1);
    const float* gsrc0 = gx0 + ((size_t)(b0 + 0) * NT) * 256 + l * 4;
    const float* gsrc1 = gx0 + ((size_t)(b0 + 1) * NT) * 256 + l * 4;
    if (isload) {
#pragma unroll
        for (int p = 0; p < PF; p++) {
            cp_async16(&gxs[p][0][l * 4], gsrc0 + (size_t)p * 256);
            cp_async16(&gxs[p][1][l * 4], gsrc1 + (size_t)p * 256);
            asm volatile("cp.async.commit_group;");
        }
        asm volatile("cp.async.wait_group %0;" :: "n"(PF - 1));
    }
    __syncthreads();

    float cs0 = 0.f, cs1 = 0.f;   // recurrent cell state for lane cl (role-dependent)

#pragma unroll 1
    for (int n = 0; n <= NT; n++) {
        __syncthreads();                       // partials(n-1) + h-writes visible
        const int pr = (n + 1) & 1;            // (n-1)&1

        // ---- CELL phase (redundant per warp, lanes it needs) ----
        if (isH1cell) {
            if (n >= 1) {
                const float* gb = &gxs[(n - 1) & 7][0][0];
                {
                    const float4 a = *reinterpret_cast<const float4*>(&p0buf[pr][0][0][cl][0]);
                    const float4 b = *reinterpret_cast<const float4*>(&p0buf[pr][1][0][cl][0]);
                    const float gi = a.x + b.x + gb[cl];
                    const float gf = a.y + b.y + gb[64 + cl];
                    const float gg = a.z + b.z + gb[128 + cl];
                    const float go = a.w + b.w + gb[192 + cl];
                    cs0 = fsig(gf) * cs0 + fsig(gi) * ftanh(gg);
                    priv[wid][0][lane] = fsig(go) * ftanh(cs0);
                }
                const float* gc = &gxs[(n - 1) & 7][1][0];
                {
                    const float4 a = *reinterpret_cast<const float4*>(&p0buf[pr][0][1][cl][0]);
                    const float4 b = *reinterpret_cast<const float4*>(&p0buf[pr][1][1][cl][0]);
                    const float gi = a.x + b.x + gc[cl];
                    const float gf = a.y + b.y + gc[64 + cl];
                    const float gg = a.z + b.z + gc[128 + cl];
                    const float go = a.w + b.w + gc[192 + cl];
                    cs1 = fsig(gf) * cs1 + fsig(gi) * ftanh(gg);
                    priv[wid][1][lane] = fsig(go) * ftanh(cs1);
                }
            }
        } else {
            if (n >= 2) {
#pragma unroll
                for (int s = 0; s < 2; s++) {
                    const float4 a0 = *reinterpret_cast<const float4*>(&p1buf[pr][0][s][cl][0]);
                    const float4 a1 = *reinterpret_cast<const float4*>(&p1buf[pr][1][s][cl][0]);
                    const float4 a2 = *reinterpret_cast<const float4*>(&p1buf[pr][2][s][cl][0]);
                    const float4 a3 = *reinterpret_cast<const float4*>(&p1buf[pr][3][s][cl][0]);
                    const float gi = ((a0.x + a1.x) + a2.x) + a3.x + bi;
                    const float gf = ((a0.y + a1.y) + a2.y) + a3.y + bf_;
                    const float gg = ((a0.z + a1.z) + a2.z) + a3.z + bg;
                    const float go = ((a0.w + a1.w) + a2.w) + a3.w + bo;
                    float& cs = s ? cs1 : cs0;
                    cs = fsig(gf) * cs + fsig(gi) * ftanh(gg);
                    priv[wid][s][lane] = fsig(go) * ftanh(cs);
                }
            }
        }
        __syncwarp();                          // own slice visible to own warp

        // ---- DOT phase ----
        const bool doDot = isL0 ? (n <= NT - 1) : (n >= 1);
        if (doDot) {
#pragma unroll
            for (int s = 0; s < 2; s++) {
                const ulonglong2* u =
                    reinterpret_cast<const ulonglong2*>(&priv[wid][s][0]);
                ull A0 = 0, A1 = 0, A2 = 0, A3 = 0;
#pragma unroll
                for (int i = 0; i < 8; i++) {
                    const ulonglong2 v = u[i];   // warp-uniform broadcast
                    ffma2(A0, v.x, w[0][2 * i]); ffma2(A0, v.y, w[0][2 * i + 1]);
                    ffma2(A1, v.x, w[1][2 * i]); ffma2(A1, v.y, w[1][2 * i + 1]);
                    ffma2(A2, v.x, w[2][2 * i]); ffma2(A2, v.y, w[2][2 * i + 1]);
                    ffma2(A3, v.x, w[3][2 * i]); ffma2(A3, v.y, w[3][2 * i + 1]);
                }
                const float2 f0 = unpackf2(A0);
                const float2 f1 = unpackf2(A1);
                const float2 f2 = unpackf2(A2);
                const float2 f3 = unpackf2(A3);
                const float4 p4 = make_float4(f0.x + f0.y, f1.x + f1.y,
                                              f2.x + f2.y, f3.x + f3.y);
                if (isL0) *reinterpret_cast<float4*>(&p0buf[n & 1][q][s][l][0]) = p4;
                else      *reinterpret_cast<float4*>(&p1buf[n & 1][kq][s][l][0]) = p4;
            }
        }

        // ---- gx ring refill (L0 q==1 warps) ----
        if (isload) {
            if (n >= 1 && n + PF - 1 < NT) {
                cp_async16(&gxs[(n + PF - 1) & 7][0][l * 4],
                           gsrc0 + (size_t)(n + PF - 1) * 256);
                cp_async16(&gxs[(n + PF - 1) & 7][1][l * 4],
                           gsrc1 + (size_t)(n + PF - 1) * 256);
            }
            asm volatile("cp.async.commit_group;");
            asm volatile("cp.async.wait_group %0;" :: "n"(PF - 1));
        }
    }

    // ---- epilogue: final h2(NT-1) cell from partials(NT), then FC ----
    __syncthreads();
    if (!isL0 && kq >= 2) {
        const int pr = NT & 1;
#pragma unroll
        for (int s = 0; s < 2; s++) {
            const float4 a0 = *reinterpret_cast<const float4*>(&p1buf[pr][0][s][cl][0]);
            const float4 a1 = *reinterpret_cast<const float4*>(&p1buf[pr][1][s][cl][0]);
            const float4 a2 = *reinterpret_cast<const float4*>(&p1buf[pr][2][s][cl][0]);
            const float4 a3 = *reinterpret_cast<const float4*>(&p1buf[pr][3][s][cl][0]);
            const float gi = ((a0.x + a1.x) + a2.x) + a3.x + bi;
            const float gf = ((a0.y + a1.y) + a2.y) + a3.y + bf_;
            const float gg = ((a0.z + a1.z) + a2.z) + a3.z + bg;
            const float go = ((a0.w + a1.w) + a2.w) + a3.w + bo;
            float& cs = s ? cs1 : cs0;
            cs = fsig(gf) * cs + fsig(gi) * ftanh(gg);
            red[s][cl] = (fsig(go) * ftanh(cs)) * w_fc[cl];   // redundant same-value write
        }
    }
    __syncthreads();
    if (tid < 64) {
        const int s_ = tid >> 5, ln = tid & 31;
        float p = red[s_][ln] + red[s_][ln + 32];
#pragma unroll
        for (int o = 16; o > 0; o >>= 1)
            p += __shfl_down_sync(0xffffffffu, p, o);
        if (ln == 0) out[b0 + s_] = fsig(p + b_fc[0]);
    }
}

extern "C" void kernel_launch(void* const* d_in, const int* in_sizes, int n_in,
                              void* d_out, int out_size) {
    const float* x       = (const float*)d_in[0];
    const float* w_ih_l0 = (const float*)d_in[1];
    const float* w_hh_l0 = (const float*)d_in[2];
    const float* b_ih_l0 = (const float*)d_in[3];
    const float* b_hh_l0 = (const float*)d_in[4];
    const float* w_ih_l1 = (const float*)d_in[5];
    const float* w_hh_l1 = (const float*)d_in[6];
    const float* b_ih_l1 = (const float*)d_in[7];
    const float* b_hh_l1 = (const float*)d_in[8];
    const float* w_fc    = (const float*)d_in[9];
    const float* b_fc    = (const float*)d_in[10];
    float* out = (float*)d_out;

    float* gx0;
    cudaGetSymbolAddress((void**)&gx0, g_gx0);

    gate_gemm32<<<NM / 64, 256>>>(x, w_ih_l0, b_ih_l0, b_hh_l0, gx0);
    lstm_fused<<<NB / 2, 384>>>(gx0, w_hh_l0, w_ih_l1, w_hh_l1,
                                b_ih_l1, b_hh_l1, w_fc, b_fc, out);
}

// round 15
// speedup vs baseline: 1.0710x; 1.0710x over previous
#include <cuda_runtime.h>

#define NB 256
#define NT 1024
#define ND0 32
#define NH 64
#define NM (NB * NT)

__device__ float g_gx0[(size_t)NM * 256];   // L0 gate pre-activations [tok][gate]

using ull = unsigned long long;

__device__ __forceinline__ void ffma2(ull& d, ull a, ull b) {
    asm("fma.rn.f32x2 %0, %1, %2, %0;" : "+l"(d) : "l"(a), "l"(b));
}
__device__ __forceinline__ ull packf2(float x, float y) {
    ull r; asm("mov.b64 %0, {%1, %2};" : "=l"(r) : "f"(x), "f"(y)); return r;
}
__device__ __forceinline__ float2 unpackf2(ull v) {
    float2 f; asm("mov.b64 {%0, %1}, %2;" : "=f"(f.x), "=f"(f.y) : "l"(v)); return f;
}
__device__ __forceinline__ float ftanh(float x) {
    float y; asm("tanh.approx.f32 %0, %1;" : "=f"(y) : "f"(x)); return y;
}
__device__ __forceinline__ float fsig(float x) {
    return fmaf(0.5f, ftanh(0.5f * x), 0.5f);
}
__device__ __forceinline__ void cp_async16(void* s, const void* g) {
    unsigned sa = (unsigned)__cvta_generic_to_shared(s);
    asm volatile("cp.async.cg.shared.global [%0], [%1], 16;" :: "r"(sa), "l"(g));
}

// ===================== layer-0 gate GEMM (proven, unchanged) =====================
__global__ __launch_bounds__(256) void gate_gemm32(
    const float* __restrict__ X,     // [M][32]
    const float* __restrict__ w_ih,  // [256][32]
    const float* __restrict__ b_ih,
    const float* __restrict__ b_hh,
    float* __restrict__ gx)          // [M][256]
{
    __shared__ __align__(16) ull   xdup[32][80];
    __shared__ __align__(16) float wT[32][264];

    const int tid = threadIdx.x;
    const size_t tok0 = (size_t)blockIdx.x * 64;

#pragma unroll
    for (int j = 0; j < 2; j++) {
        const int idx4 = tid + j * 256;
        const int tau = idx4 >> 3, kc = idx4 & 7;
        const int ts = tau + 2 * (tau >> 3);
        const float4 v = reinterpret_cast<const float4*>(X + (tok0 + tau) * 32)[kc];
        xdup[4 * kc + 0][ts] = packf2(v.x, v.x);
        xdup[4 * kc + 1][ts] = packf2(v.y, v.y);
        xdup[4 * kc + 2][ts] = packf2(v.z, v.z);
        xdup[4 * kc + 3][ts] = packf2(v.w, v.w);
    }
    {
        const float4* wr = reinterpret_cast<const float4*>(w_ih + tid * 32);
#pragma unroll
        for (int c = 0; c < 8; c++) {
            const float4 v = wr[c];
            wT[4 * c + 0][tid] = v.x;
            wT[4 * c + 1][tid] = v.y;
            wT[4 * c + 2][tid] = v.z;
            wT[4 * c + 3][tid] = v.w;
        }
    }

    const int tokg = tid & 7;
    const int gg   = tid >> 3;
    const int t0s = tokg * 10;
    const int t0  = tokg * 8;
    const int g0  = gg * 8;

    ull acc[8][4];
#pragma unroll
    for (int p = 0; p < 4; p++) {
        const ull bp = packf2(b_ih[g0 + 2 * p]     + b_hh[g0 + 2 * p],
                              b_ih[g0 + 2 * p + 1] + b_hh[g0 + 2 * p + 1]);
#pragma unroll
        for (int tk = 0; tk < 8; tk++) acc[tk][p] = bp;
    }

    __syncthreads();

#pragma unroll 4
    for (int k = 0; k < 32; k++) {
        const ulonglong2 wa = *reinterpret_cast<const ulonglong2*>(&wT[k][g0]);
        const ulonglong2 wb = *reinterpret_cast<const ulonglong2*>(&wT[k][g0 + 4]);
        const ull w01[4] = {wa.x, wa.y, wb.x, wb.y};
        const ulonglong2* xr = reinterpret_cast<const ulonglong2*>(&xdup[k][t0s]);
#pragma unroll
        for (int h = 0; h < 4; h++) {
            const ulonglong2 xv = xr[h];
#pragma unroll
            for (int p = 0; p < 4; p++) {
                ffma2(acc[2 * h][p],     xv.x, w01[p]);
                ffma2(acc[2 * h + 1][p], xv.y, w01[p]);
            }
        }
    }

#pragma unroll
    for (int tk = 0; tk < 8; tk++) {
        ulonglong2* dst =
            reinterpret_cast<ulonglong2*>(gx + (tok0 + t0 + tk) * 256 + g0);
        dst[0] = make_ulonglong2(acc[tk][0], acc[tk][1]);
        dst[1] = make_ulonglong2(acc[tk][2], acc[tk][3]);
    }
}

// ========== fused L0+L1: layer-interleaved phases ==========
// 384 thr. L0 = tid<128 (q=k-half, l=gate-lane). L1 = tid>=128 (kq=k-quarter, l).
// Phase1(n): L0 dots(n) [FMA] + L1 cells -> h2(n-2) [kq<2, MUFU] + gx loaders [kq>=2].
// Phase2(n): L0 cells(n) -> h1(n) [1 cell/thread, sample=q] + L1 dots over
//            [h1(n-1); h2(n-2)] [FMA].
// Single-buffered p0buf/p1buf (write/read alternate phases); ubuf parity-double.
__global__ __launch_bounds__(384) void lstm_fused(
    const float* __restrict__ gx0,    // [B][T][256] (with L0 biases)
    const float* __restrict__ w_hh0,  // [256][64]
    const float* __restrict__ w_ih1,  // [256][64]
    const float* __restrict__ w_hh1,  // [256][64]
    const float* __restrict__ b_ih1,  // [256]
    const float* __restrict__ b_hh1,  // [256]
    const float* __restrict__ w_fc,   // [64]
    const float* __restrict__ b_fc,   // [1]
    float* __restrict__ out)          // [B]
{
    constexpr int PF = 7;

    __shared__ __align__(16) float ubuf[2][2][128];    // [par][sample][h1|h2]
    __shared__ __align__(16) float gxs[8][2][256];     // gx0 ring
    __shared__ __align__(16) float p0buf[2][2][64][4]; // [q][s][l][gate]
    __shared__ __align__(16) float p1buf[4][2][64][4]; // [kq][s][l][gate]
    __shared__ float red[2][NH];

    const int tid  = threadIdx.x;
    const int b0   = blockIdx.x * 2;
    const bool isL0 = (tid < 128);

    for (int i = tid; i < 2 * 2 * 128; i += 384) (&ubuf[0][0][0])[i] = 0.0f;

    const int q  = (tid >> 6) & 1;     // L0 k-half    (warp-constant)
    const int rt = tid - 128;
    const int kq = rt >> 6;            // L1 k-quarter (warp-constant)
    const int l  = tid & 63;

    // ---- weights: 4 gate rows of lane l, my k-slice -> 128 regs ----
    ull w[4][16];
    float bi = 0.f, bf_ = 0.f, bg = 0.f, bo = 0.f;
    if (isL0) {
#pragma unroll
        for (int g4 = 0; g4 < 4; g4++) {
            const int row = 64 * g4 + l;
#pragma unroll
            for (int i = 0; i < 16; i++) {
                const int k = 32 * q + 2 * i;
                w[g4][i] = packf2(w_hh0[row * NH + k], w_hh0[row * NH + k + 1]);
            }
        }
    } else {
#pragma unroll
        for (int g4 = 0; g4 < 4; g4++) {
            const int row = 64 * g4 + l;
#pragma unroll
            for (int i = 0; i < 16; i++) {
                const int kk = 32 * kq + 2 * i;
                const float a = (kk < 64) ? w_ih1[row * 64 + kk]
                                          : w_hh1[row * 64 + kk - 64];
                const float b = (kk < 64) ? w_ih1[row * 64 + kk + 1]
                                          : w_hh1[row * 64 + kk - 63];
                w[g4][i] = packf2(a, b);
            }
        }
        if (kq < 2) {   // L1 cell threads (sample = kq)
            bi  = b_ih1[l]       + b_hh1[l];
            bf_ = b_ih1[64 + l]  + b_hh1[64 + l];
            bg  = b_ih1[128 + l] + b_hh1[128 + l];
            bo  = b_ih1[192 + l] + b_hh1[192 + l];
        }
    }

    // gx ring loaders: L1 kq>=2 warps (idle during phase-1 cells)
    const bool isload = !isL0 && (kq >= 2);
    const int  lsmp   = kq - 2;
    const float* gsrc = gx0 + ((size_t)(b0 + (isload ? lsmp : 0)) * NT) * 256 + l * 4;
    if (isload) {
#pragma unroll
        for (int p = 0; p < PF; p++) {
            cp_async16(&gxs[p][lsmp][l * 4], gsrc + (size_t)p * 256);
            asm volatile("cp.async.commit_group;");
        }
        asm volatile("cp.async.wait_group %0;" :: "n"(PF - 1));
    }
    __syncthreads();

    float cs = 0.f;                    // L0 cell state (sample q) / unused
    float ds = 0.f, h_last = 0.f;      // L1 cell state (sample kq<2)

#pragma unroll 1
    for (int n = 0; n <= NT; n++) {
        const int prv = (n + 1) & 1;   // (n-1)&1

        // ================= PHASE 1 =================
        if (isL0) {
            if (n < NT) {
                // L0 dots(n): u = h1(n-1), slice 32q..32q+31
                const ulonglong2* ub[2] = {
                    reinterpret_cast<const ulonglong2*>(&ubuf[prv][0][32 * q]),
                    reinterpret_cast<const ulonglong2*>(&ubuf[prv][1][32 * q])};
#pragma unroll
                for (int s = 0; s < 2; s++) {
                    const ulonglong2* u = ub[s];
                    ull A0 = 0, A1 = 0, A2 = 0, A3 = 0;
#pragma unroll
                    for (int i = 0; i < 8; i++) {
                        const ulonglong2 v = u[i];
                        ffma2(A0, v.x, w[0][2 * i]); ffma2(A0, v.y, w[0][2 * i + 1]);
                        ffma2(A1, v.x, w[1][2 * i]); ffma2(A1, v.y, w[1][2 * i + 1]);
                        ffma2(A2, v.x, w[2][2 * i]); ffma2(A2, v.y, w[2][2 * i + 1]);
                        ffma2(A3, v.x, w[3][2 * i]); ffma2(A3, v.y, w[3][2 * i + 1]);
                    }
                    const float2 f0 = unpackf2(A0);
                    const float2 f1 = unpackf2(A1);
                    const float2 f2 = unpackf2(A2);
                    const float2 f3 = unpackf2(A3);
                    *reinterpret_cast<float4*>(&p0buf[q][s][l][0]) =
                        make_float4(f0.x + f0.y, f1.x + f1.y,
                                    f2.x + f2.y, f3.x + f3.y);
                }
            }
        } else if (kq < 2) {
            // L1 cell: h2(n-2), sample kq
            if (n >= 2) {
                const int s = kq;
                const float4 a0 = *reinterpret_cast<const float4*>(&p1buf[0][s][l][0]);
                const float4 a1 = *reinterpret_cast<const float4*>(&p1buf[1][s][l][0]);
                const float4 a2 = *reinterpret_cast<const float4*>(&p1buf[2][s][l][0]);
                const float4 a3 = *reinterpret_cast<const float4*>(&p1buf[3][s][l][0]);
                const float gi = ((a0.x + a1.x) + a2.x) + a3.x + bi;
                const float gf = ((a0.y + a1.y) + a2.y) + a3.y + bf_;
                const float gg = ((a0.z + a1.z) + a2.z) + a3.z + bg;
                const float go = ((a0.w + a1.w) + a2.w) + a3.w + bo;
                ds = fsig(gf) * ds + fsig(gi) * ftanh(gg);
                h_last = fsig(go) * ftanh(ds);
                ubuf[prv][s][64 + l] = h_last;    // h2(n-2) at parity (n-1)&1
            }
        } else {
            // gx ring refill
            if (n >= 1 && n + PF - 1 < NT)
                cp_async16(&gxs[(n + PF - 1) & 7][lsmp][l * 4],
                           gsrc + (size_t)(n + PF - 1) * 256);
            asm volatile("cp.async.commit_group;");
            asm volatile("cp.async.wait_group %0;" :: "n"(PF - 1));
        }
        __syncthreads();

        // ================= PHASE 2 =================
        if (isL0) {
            if (n < NT) {
                // L0 cell(n): ONE cell per thread, sample = q
                const int s = q;
                const float* gb = &gxs[n & 7][s][0];
                const float4 a = *reinterpret_cast<const float4*>(&p0buf[0][s][l][0]);
                const float4 b = *reinterpret_cast<const float4*>(&p0buf[1][s][l][0]);
                const float gi = a.x + b.x + gb[l];
                const float gf = a.y + b.y + gb[64 + l];
                const float gg = a.z + b.z + gb[128 + l];
                const float go = a.w + b.w + gb[192 + l];
                cs = fsig(gf) * cs + fsig(gi) * ftanh(gg);
                ubuf[n & 1][s][l] = fsig(go) * ftanh(cs);   // h1(n)
            }
        } else {
            if (n >= 1) {
                // L1 dots: u = [h1(n-1) | h2(n-2)] at parity (n-1)&1
                const ulonglong2* ub[2] = {
                    reinterpret_cast<const ulonglong2*>(&ubuf[prv][0][32 * kq]),
                    reinterpret_cast<const ulonglong2*>(&ubuf[prv][1][32 * kq])};
#pragma unroll
                for (int s = 0; s < 2; s++) {
                    const ulonglong2* u = ub[s];
                    ull A0 = 0, A1 = 0, A2 = 0, A3 = 0;
#pragma unroll
                    for (int i = 0; i < 8; i++) {
                        const ulonglong2 v = u[i];
                        ffma2(A0, v.x, w[0][2 * i]); ffma2(A0, v.y, w[0][2 * i + 1]);
                        ffma2(A1, v.x, w[1][2 * i]); ffma2(A1, v.y, w[1][2 * i + 1]);
                        ffma2(A2, v.x, w[2][2 * i]); ffma2(A2, v.y, w[2][2 * i + 1]);
                        ffma2(A3, v.x, w[3][2 * i]); ffma2(A3, v.y, w[3][2 * i + 1]);
                    }
                    const float2 f0 = unpackf2(A0);
                    const float2 f1 = unpackf2(A1);
                    const float2 f2 = unpackf2(A2);
                    const float2 f3 = unpackf2(A3);
                    *reinterpret_cast<float4*>(&p1buf[kq][s][l][0]) =
                        make_float4(f0.x + f0.y, f1.x + f1.y,
                                    f2.x + f2.y, f3.x + f3.y);
                }
            }
        }
        __syncthreads();
    }

    // ---- epilogue: h2(NT-1) from partials(n=NT), then FC + sigmoid ----
    if (!isL0 && kq < 2) {
        const int s = kq;
        const float4 a0 = *reinterpret_cast<const float4*>(&p1buf[0][s][l][0]);
        const float4 a1 = *reinterpret_cast<const float4*>(&p1buf[1][s][l][0]);
        const float4 a2 = *reinterpret_cast<const float4*>(&p1buf[2][s][l][0]);
        const float4 a3 = *reinterpret_cast<const float4*>(&p1buf[3][s][l][0]);
        const float gi = ((a0.x + a1.x) + a2.x) + a3.x + bi;
        const float gf = ((a0.y + a1.y) + a2.y) + a3.y + bf_;
        const float gg = ((a0.z + a1.z) + a2.z) + a3.z + bg;
        const float go = ((a0.w + a1.w) + a2.w) + a3.w + bo;
        ds = fsig(gf) * ds + fsig(gi) * ftanh(gg);
        red[s][l] = (fsig(go) * ftanh(ds)) * w_fc[l];
    }
    __syncthreads();
    if (tid < 64) {
        const int s_ = tid >> 5, ln = tid & 31;
        float p = red[s_][ln] + red[s_][ln + 32];
#pragma unroll
        for (int o = 16; o > 0; o >>= 1)
            p += __shfl_down_sync(0xffffffffu, p, o);
        if (ln == 0) out[b0 + s_] = fsig(p + b_fc[0]);
    }
}

extern "C" void kernel_launch(void* const* d_in, const int* in_sizes, int n_in,
                              void* d_out, int out_size) {
    const float* x       = (const float*)d_in[0];
    const float* w_ih_l0 = (const float*)d_in[1];
    const float* w_hh_l0 = (const float*)d_in[2];
    const float* b_ih_l0 = (const float*)d_in[3];
    const float* b_hh_l0 = (const float*)d_in[4];
    const float* w_ih_l1 = (const float*)d_in[5];
    const float* w_hh_l1 = (const float*)d_in[6];
    const float* b_ih_l1 = (const float*)d_in[7];
    const float* b_hh_l1 = (const float*)d_in[8];
    const float* w_fc    = (const float*)d_in[9];
    const float* b_fc    = (const float*)d_in[10];
    float* out = (float*)d_out;

    float* gx0;
    cudaGetSymbolAddress((void**)&gx0, g_gx0);

    gate_gemm32<<<NM / 64, 256>>>(x, w_ih_l0, b_ih_l0, b_hh_l0, gx0);
    lstm_fused<<<NB / 2, 384>>>(gx0, w_hh_l0, w_ih_l1, w_hh_l1,
                                b_ih_l1, b_hh_l1, w_fc, b_fc, out);
}